// round 15
// baseline (speedup 1.0000x reference)
#include <cuda_runtime.h>
#include <cuda_fp16.h>
#include <cstdint>

// Problem constants
#define T_TOK 8192
#define DDIM  4096
#define ODIM  4096
#define LMAX  8
#define RANK  16
#define KEXT  (LMAX * RANK)     // 128 extension columns
#define KTOT  (DDIM + KEXT)     // 4224

// ---------------------------------------------------------------------------
// Static device scratch (no allocations allowed)
// ---------------------------------------------------------------------------
__device__ __half g_xh[(size_t)T_TOK * DDIM];      // x  in fp16 (written by shrink)
__device__ __half g_wh[(size_t)ODIM * DDIM];       // W  in fp16
__device__ __half g_ah[(size_t)LMAX * RANK * DDIM];// A_cat [128, 4096] fp16 (1 MB)
__device__ __half g_xe[(size_t)T_TOK * KEXT];      // S~ one-hot shrink (2 MB)
__device__ __half g_we[(size_t)ODIM * KEXT];       // B_cat (1 MB)

// ---------------------------------------------------------------------------
// PTX helpers (sm_80/90-era: legal on plain sm_103 target)
// ---------------------------------------------------------------------------
__device__ __forceinline__ uint32_t smem_u32(const void* p) {
    uint32_t a;
    asm("{ .reg .u64 t; cvta.to.shared.u64 t, %1; cvt.u32.u64 %0, t; }"
        : "=r"(a) : "l"(p));
    return a;
}
__device__ __forceinline__ void cp16(uint32_t d, const void* g) {
    asm volatile("cp.async.cg.shared.global [%0], [%1], 16;"
                 :: "r"(d), "l"(g) : "memory");
}
__device__ __forceinline__ void ldsm4(uint32_t* r, uint32_t a) {
    asm volatile("ldmatrix.sync.aligned.m8n8.x4.shared.b16 {%0,%1,%2,%3}, [%4];"
                 : "=r"(r[0]), "=r"(r[1]), "=r"(r[2]), "=r"(r[3]) : "r"(a));
}
__device__ __forceinline__ void mma_fp16(float* c, const uint32_t* a,
                                         uint32_t b0, uint32_t b1) {
    asm volatile(
        "mma.sync.aligned.m16n8k16.row.col.f32.f16.f16.f32 "
        "{%0,%1,%2,%3}, {%4,%5,%6,%7}, {%8,%9}, {%0,%1,%2,%3};"
        : "+f"(c[0]), "+f"(c[1]), "+f"(c[2]), "+f"(c[3])
        : "r"(a[0]), "r"(a[1]), "r"(a[2]), "r"(a[3]), "r"(b0), "r"(b1));
}

// ---------------------------------------------------------------------------
// conv_all: one launch for all fp32->fp16 conversions (pure bandwidth).
//   blocks [0,512):    W  -> g_wh
//   blocks [512,640):  lora_a -> g_ah   (A_cat rows = [l][r] flattened)
//   blocks [640,768):  lora_b -> g_we   (B_cat: g_we[o, l*16+r] = lb[l,o,r])
// ---------------------------------------------------------------------------
__global__ void conv_all(const float* __restrict__ w,
                         const float* __restrict__ la,
                         const float* __restrict__ lb) {
    const int b = blockIdx.x;
    const int tid = threadIdx.x;
    if (b < 512) {
        size_t n4 = (size_t)ODIM * DDIM / 4;           // 4,194,304
        const float4* in4 = reinterpret_cast<const float4*>(w);
        for (size_t i = (size_t)b * 256 + tid; i < n4; i += (size_t)512 * 256) {
            float4 v = in4[i];
            reinterpret_cast<__half2*>(g_wh)[i * 2]     = __floats2half2_rn(v.x, v.y);
            reinterpret_cast<__half2*>(g_wh)[i * 2 + 1] = __floats2half2_rn(v.z, v.w);
        }
    } else if (b < 640) {
        const int cb = b - 512;                        // lora_a: 131072 float4
        const float4* in4 = reinterpret_cast<const float4*>(la);
#pragma unroll
        for (int it = 0; it < 4; it++) {
            const size_t i = (size_t)it * 32768 + cb * 256 + tid;
            float4 v = in4[i];
            reinterpret_cast<__half2*>(g_ah)[i * 2]     = __floats2half2_rn(v.x, v.y);
            reinterpret_cast<__half2*>(g_ah)[i * 2 + 1] = __floats2half2_rn(v.z, v.w);
        }
    } else {
        const int i = (b - 640) * 256 + tid;           // over ODIM*LMAX = 32768
        const int o = i >> 3;
        const int l = i & 7;
        const float4* src = reinterpret_cast<const float4*>(lb + ((size_t)l * ODIM + o) * RANK);
        __half2 h[8];
#pragma unroll
        for (int q = 0; q < 4; q++) {
            float4 v = src[q];
            h[q * 2]     = __floats2half2_rn(v.x, v.y);
            h[q * 2 + 1] = __floats2half2_rn(v.z, v.w);
        }
        __half2* dst = reinterpret_cast<__half2*>(g_we + (size_t)o * KEXT + l * RANK);
        *reinterpret_cast<uint4*>(dst)     = *reinterpret_cast<uint4*>(h);
        *reinterpret_cast<uint4*>(dst + 4) = *reinterpret_cast<uint4*>(h + 4);
    }
}

// ---------------------------------------------------------------------------
// Dense tensor-core shrink: S_full = x @ A_cat^T for ALL adapters, then
// one-hot mask in the epilogue. Block = 64 consecutive tokens, 256 threads.
// No gather, no token lists. Also emits g_xh (x in fp16).
//   xt: 64 x 128B (8 KB) x2 ; at: 128 x 128B (16 KB) x2  => 48 KB SMEM
//   Warps 0-3: m-tile = wid*16 tokens, n = 128 (16 n8 accumulators).
// ---------------------------------------------------------------------------
#define SH_CH   (DDIM / 64)          // 64 chunks
#define XT_B    (64 * 128)           // 8 KB
#define AT2_B   (128 * 128)          // 16 KB

__global__ __launch_bounds__(256)
void shrink_dense(const float* __restrict__ x, const int* __restrict__ idx_g) {
    __shared__ __align__(16) char xt[2][XT_B];
    __shared__ __align__(16) char at[2][AT2_B];
    __shared__ int lidx[64];

    const int t0 = blockIdx.x * 64;
    const int tid = threadIdx.x;
    const int wid = tid >> 5;
    const int lane = tid & 31;

    if (tid < 64) lidx[tid] = idx_g[t0 + tid];

    const uint32_t xt0 = smem_u32(&xt[0][0]);
    const uint32_t at0 = smem_u32(&at[0][0]);

    auto stage_a = [&](int ch) {
        const uint32_t dst = at0 + (uint32_t)(ch & 1) * AT2_B;
#pragma unroll
        for (int it = 0; it < 4; it++) {               // 1024 cp16 (128 rows x 8)
            const int u = it * 256 + tid;
            const int r = u >> 3;
            const int c = u & 7;
            cp16(dst + r * 128 + ((c ^ (r & 7)) << 4),
                 g_ah + (size_t)r * DDIM + ch * 64 + c * 8);
        }
        asm volatile("cp.async.commit_group;" ::: "memory");
    };

    const int u0r = tid >> 3, u0c = tid & 7;          // x unit 0
    const int u1r = (tid + 256) >> 3, u1c = tid & 7;  // x unit 1

    float acc[16][4];
#pragma unroll
    for (int n = 0; n < 16; n++)
#pragma unroll
        for (int q = 0; q < 4; q++) acc[n][q] = 0.f;

    const int a_r = lane & 15;
    const int a_h = lane >> 4;
    const int b_r = (lane & 7) + ((lane >> 4) << 3);
    const int b_h = (lane >> 3) & 1;

    stage_a(0);
    stage_a(1);
    __syncthreads();                                  // lidx visible

    for (int ch = 0; ch < SH_CH; ch++) {
        const int buf = ch & 1;
        // 1. LDG fp32 x (coalesced, consecutive tokens) + convert
        uint4 pk[2];
#pragma unroll
        for (int u = 0; u < 2; u++) {
            const int r = u ? u1r : u0r;
            const int c = u ? u1c : u0c;
            const float4* src = reinterpret_cast<const float4*>(
                x + (size_t)(t0 + r) * DDIM + ch * 64 + c * 8);
            float4 v0 = src[0], v1 = src[1];
            __half2 h0 = __floats2half2_rn(v0.x, v0.y);
            __half2 h1 = __floats2half2_rn(v0.z, v0.w);
            __half2 h2 = __floats2half2_rn(v1.x, v1.y);
            __half2 h3 = __floats2half2_rn(v1.z, v1.w);
            pk[u].x = *reinterpret_cast<uint32_t*>(&h0);
            pk[u].y = *reinterpret_cast<uint32_t*>(&h1);
            pk[u].z = *reinterpret_cast<uint32_t*>(&h2);
            pk[u].w = *reinterpret_cast<uint32_t*>(&h3);
        }
        // 2. A_cat tile resident
        if (ch < SH_CH - 1)
            asm volatile("cp.async.wait_group 1;" ::: "memory");
        else
            asm volatile("cp.async.wait_group 0;" ::: "memory");
        // 3. STS x (swizzled) + STG fp16 to g_xh
#pragma unroll
        for (int u = 0; u < 2; u++) {
            const int r = u ? u1r : u0r;
            const int c = u ? u1c : u0c;
            *reinterpret_cast<uint4*>(&xt[buf][r * 128 + ((c ^ (r & 7)) << 4)]) = pk[u];
            *reinterpret_cast<uint4*>(g_xh + (size_t)(t0 + r) * DDIM + ch * 64 + c * 8) = pk[u];
        }
        __syncthreads();
        // 4. MMA: m16 (tokens) x n128 (all adapters' ranks)
        if (wid < 4) {
            const uint32_t Xb = xt0 + (uint32_t)buf * XT_B;
            const uint32_t Ab = at0 + (uint32_t)buf * AT2_B;
#pragma unroll
            for (int ks = 0; ks < 4; ks++) {
                uint32_t af[4];
                const int rowa = wid * 16 + a_r;
                const int cla = ks * 2 + a_h;
                ldsm4(af, Xb + rowa * 128 + ((cla ^ (rowa & 7)) << 4));
#pragma unroll
                for (int p = 0; p < 8; p++) {
                    uint32_t bf[4];
                    const int rowb = p * 16 + b_r;
                    const int clb = ks * 2 + b_h;
                    ldsm4(bf, Ab + rowb * 128 + ((clb ^ (rowb & 7)) << 4));
                    mma_fp16(acc[2 * p],     af, bf[0], bf[1]);
                    mma_fp16(acc[2 * p + 1], af, bf[2], bf[3]);
                }
            }
        }
        __syncthreads();
        if (ch + 2 < SH_CH) stage_a(ch + 2);
    }

    // Epilogue: one-hot mask + fp16 store. Row r keeps segment lidx[r] only.
    if (wid < 4) {
        const int er = lane >> 2;
        const int ec = (lane & 3) * 2;
#pragma unroll
        for (int half = 0; half < 2; half++) {
            const int r = wid * 16 + er + half * 8;
            const int t = t0 + r;
            const int l = lidx[r];
#pragma unroll
            for (int nt = 0; nt < 16; nt++) {
                __half2 v = ((nt >> 1) == l)
                    ? __floats2half2_rn(acc[nt][half * 2], acc[nt][half * 2 + 1])
                    : __floats2half2_rn(0.f, 0.f);
                *reinterpret_cast<__half2*>(g_xe + (size_t)t * KEXT + nt * 8 + ec) = v;
            }
        }
    }
}

// ---------------------------------------------------------------------------
// Fused GEMM: out = [x | S~] @ [W | B_cat]^T   (fp16 mma.sync, fp32 accum)
// 128x256 CTA tile, BK=64, 4-stage cp.async pipeline (192 KB SMEM), 8 warps.
// Cross-chunk fragment prefetch. (R9/R12/R13-proven — frozen.)
// ---------------------------------------------------------------------------
#define BKC     64
#define NCHUNKC (KTOT / BKC)                  // 66
#define A_TILEB (128 * 128)
#define B_TILEB (256 * 128)
#define STAGEB  (A_TILEB + B_TILEB)           // 48 KB
#define STAGES  4
#define GEMM_SMEM (STAGES * STAGEB)           // 192 KB

__global__ __launch_bounds__(256, 1)
void gemm_mma(float* __restrict__ C) {
    extern __shared__ char smem[];
    const uint32_t sb = smem_u32(smem);
    const int tid  = threadIdx.x;
    const int wid  = tid >> 5;
    const int lane = tid & 31;

    const int bid = blockIdx.x;
    const int TN = ODIM / 256;                 // 16
    const int GRP = 8;
    const int per = GRP * TN;                  // 128
    const int m_t = (bid / per) * GRP + (bid % per) % GRP;
    const int n_t = (bid % per) / GRP;
    const int bm = m_t * 128;
    const int bn = n_t * 256;

    const int warp_m = wid & 1;
    const int warp_n = wid >> 1;

    auto issue_chunk = [&](int chunk, int stage) {
        const int k0 = chunk * BKC;
        const bool ext = (k0 >= DDIM);
        const __half* asrc = ext ? g_xe : g_xh;
        const __half* bsrc = ext ? g_we : g_wh;
        const size_t astr = ext ? KEXT : DDIM;
        const int ak = ext ? (k0 - DDIM) : k0;
        const uint32_t sbase = sb + (uint32_t)stage * STAGEB;
#pragma unroll
        for (int rep = 0; rep < 4; rep++) {            // A: 1024 cp16
            const int idx = rep * 256 + tid;
            const int r = idx >> 3;
            const int c = idx & 7;
            const void* g = asrc + (size_t)(bm + r) * astr + ak + c * 8;
            cp16(sbase + r * 128 + ((c ^ (r & 7)) << 4), g);
        }
#pragma unroll
        for (int rep = 0; rep < 8; rep++) {            // B: 2048 cp16
            const int idx = rep * 256 + tid;
            const int r = idx >> 3;
            const int c = idx & 7;
            const void* g = bsrc + (size_t)(bn + r) * astr + ak + c * 8;
            cp16(sbase + A_TILEB + r * 128 + ((c ^ (r & 7)) << 4), g);
        }
        asm volatile("cp.async.commit_group;" ::: "memory");
    };

    const int a_r = lane & 15;
    const int a_h = lane >> 4;
    const int b_r = (lane & 7) + ((lane >> 4) << 3);
    const int b_h = (lane >> 3) & 1;

    auto load_frags = [&](int stage, int ks, uint32_t (&af)[4][4], uint32_t (&bf)[4][4]) {
        const uint32_t Ab = sb + (uint32_t)stage * STAGEB;
        const uint32_t Bb = Ab + A_TILEB;
        const int cla = ks * 2 + a_h;
        const int clb = ks * 2 + b_h;
#pragma unroll
        for (int mt = 0; mt < 4; mt++) {
            const int row = warp_m * 64 + mt * 16 + a_r;
            ldsm4(af[mt], Ab + row * 128 + ((cla ^ (row & 7)) << 4));
        }
#pragma unroll
        for (int p = 0; p < 4; p++) {
            const int row = warp_n * 64 + p * 16 + b_r;
            ldsm4(bf[p], Bb + row * 128 + ((clb ^ (row & 7)) << 4));
        }
    };

    float acc[4][8][4];
#pragma unroll
    for (int i = 0; i < 4; i++)
#pragma unroll
        for (int j = 0; j < 8; j++)
#pragma unroll
            for (int q = 0; q < 4; q++) acc[i][j][q] = 0.f;

#pragma unroll
    for (int s = 0; s < STAGES - 1; s++) issue_chunk(s, s);

    uint32_t af[2][4][4], bf[2][4][4];
    asm volatile("cp.async.wait_group %0;" :: "n"(STAGES - 2) : "memory");
    __syncthreads();
    load_frags(0, 0, af[0], bf[0]);

    for (int i = 0; i < NCHUNKC; i++) {
        const int stage = i & (STAGES - 1);
#pragma unroll
        for (int ks = 0; ks < 4; ks++) {
            const int cur = ks & 1;
            if (ks < 3) load_frags(stage, ks + 1, af[cur ^ 1], bf[cur ^ 1]);
#pragma unroll
            for (int mt = 0; mt < 4; mt++)
#pragma unroll
                for (int nt = 0; nt < 8; nt++)
                    mma_fp16(acc[mt][nt], af[cur][mt],
                             bf[cur][nt >> 1][(nt & 1) * 2],
                             bf[cur][nt >> 1][(nt & 1) * 2 + 1]);
        }
        if (i + 1 < NCHUNKC) {
            asm volatile("cp.async.wait_group 1;" ::: "memory");
            __syncthreads();
            load_frags((i + 1) & (STAGES - 1), 0, af[0], bf[0]);
            if (i + STAGES - 1 < NCHUNKC)
                issue_chunk(i + STAGES - 1, (i + STAGES - 1) & (STAGES - 1));
        }
    }

    const int er = lane >> 2;
    const int ec = (lane & 3) * 2;
#pragma unroll
    for (int mt = 0; mt < 4; mt++) {
#pragma unroll
        for (int nt = 0; nt < 8; nt++) {
            float* base = C + (size_t)(bm + warp_m * 64 + mt * 16 + er) * ODIM +
                          bn + warp_n * 64 + nt * 8 + ec;
            *reinterpret_cast<float2*>(base) =
                make_float2(acc[mt][nt][0], acc[mt][nt][1]);
            *reinterpret_cast<float2*>(base + 8 * ODIM) =
                make_float2(acc[mt][nt][2], acc[mt][nt][3]);
        }
    }
}

// ---------------------------------------------------------------------------
// Launch: inputs order: x, weight, lora_a, lora_b, token_lora_idx
// ---------------------------------------------------------------------------
extern "C" void kernel_launch(void* const* d_in, const int* in_sizes, int n_in,
                              void* d_out, int out_size) {
    const float* x   = (const float*)d_in[0];
    const float* w   = (const float*)d_in[1];
    const float* la  = (const float*)d_in[2];
    const float* lb  = (const float*)d_in[3];
    const int*   idx = (const int*)d_in[4];
    float* out = (float*)d_out;

    cudaFuncSetAttribute(gemm_mma, cudaFuncAttributeMaxDynamicSharedMemorySize,
                         GEMM_SMEM);

    conv_all<<<768, 256>>>(w, la, lb);                 // W + A_cat + B_cat fp16
    shrink_dense<<<T_TOK / 64, 256>>>(x, idx);         // S~ (masked) + g_xh
    gemm_mma<<<(T_TOK / 128) * (ODIM / 256), 256, GEMM_SMEM>>>(out);
}

// round 16
// speedup vs baseline: 1.0324x; 1.0324x over previous
#include <cuda_runtime.h>
#include <cuda_fp16.h>
#include <cstdint>

// Problem constants
#define T_TOK 8192
#define DDIM  4096
#define ODIM  4096
#define LMAX  8
#define RANK  16
#define KEXT  (LMAX * RANK)     // 128 extension columns
#define KTOT  (DDIM + KEXT)     // 4224

// ---------------------------------------------------------------------------
// Static device scratch (no allocations allowed)
// ---------------------------------------------------------------------------
__device__ __half g_xh[(size_t)T_TOK * DDIM];      // x  in fp16 (written by shrink)
__device__ __half g_wh[(size_t)ODIM * DDIM];       // W  in fp16
__device__ __half g_ah[(size_t)LMAX * RANK * DDIM];// lora_a in fp16 (1 MB)
__device__ __half g_xe[(size_t)T_TOK * KEXT];      // S~ one-hot shrink (2 MB)
__device__ __half g_we[(size_t)ODIM * KEXT];       // B_cat (1 MB)
__device__ int    g_cnt[LMAX];                     // per-adapter counts (zeroed by gemm)
__device__ int    g_tok[LMAX * T_TOK];             // per-adapter token lists

// ---------------------------------------------------------------------------
// PTX helpers (sm_80/90-era: legal on plain sm_103 target)
// ---------------------------------------------------------------------------
__device__ __forceinline__ uint32_t smem_u32(const void* p) {
    uint32_t a;
    asm("{ .reg .u64 t; cvta.to.shared.u64 t, %1; cvt.u32.u64 %0, t; }"
        : "=r"(a) : "l"(p));
    return a;
}
__device__ __forceinline__ void cp16(uint32_t d, const void* g) {
    asm volatile("cp.async.cg.shared.global [%0], [%1], 16;"
                 :: "r"(d), "l"(g) : "memory");
}
__device__ __forceinline__ void ldsm4(uint32_t* r, uint32_t a) {
    asm volatile("ldmatrix.sync.aligned.m8n8.x4.shared.b16 {%0,%1,%2,%3}, [%4];"
                 : "=r"(r[0]), "=r"(r[1]), "=r"(r[2]), "=r"(r[3]) : "r"(a));
}
__device__ __forceinline__ void mma_fp16(float* c, const uint32_t* a,
                                         uint32_t b0, uint32_t b1) {
    asm volatile(
        "mma.sync.aligned.m16n8k16.row.col.f32.f16.f16.f32 "
        "{%0,%1,%2,%3}, {%4,%5,%6,%7}, {%8,%9}, {%0,%1,%2,%3};"
        : "+f"(c[0]), "+f"(c[1]), "+f"(c[2]), "+f"(c[3])
        : "r"(a[0]), "r"(a[1]), "r"(a[2]), "r"(a[3]), "r"(b0), "r"(b1));
}

// ---------------------------------------------------------------------------
// conv_all: ONE launch for all conversions + token bucketing.
//   blocks [0,32):     build_lists role (g_cnt starts 0; gemm re-zeroes it)
//   blocks [32,544):   W  -> g_wh
//   blocks [544,672):  lora_a -> g_ah
//   blocks [672,800):  lora_b -> g_we (B_cat layout)
// ---------------------------------------------------------------------------
__global__ void conv_all(const float* __restrict__ w,
                         const float* __restrict__ la,
                         const float* __restrict__ lb,
                         const int*   __restrict__ idx) {
    const int b = blockIdx.x;
    const int tid = threadIdx.x;
    if (b < 32) {
        const int t = b * 256 + tid;                   // 8192 tokens
        const int l = idx[t];
        const int p = atomicAdd(&g_cnt[l], 1);
        g_tok[l * T_TOK + p] = t;
    } else if (b < 544) {
        const int cb = b - 32;
        size_t n4 = (size_t)ODIM * DDIM / 4;           // 4,194,304
        const float4* in4 = reinterpret_cast<const float4*>(w);
        for (size_t i = (size_t)cb * 256 + tid; i < n4; i += (size_t)512 * 256) {
            float4 v = in4[i];
            reinterpret_cast<__half2*>(g_wh)[i * 2]     = __floats2half2_rn(v.x, v.y);
            reinterpret_cast<__half2*>(g_wh)[i * 2 + 1] = __floats2half2_rn(v.z, v.w);
        }
    } else if (b < 672) {
        const int cb = b - 544;                        // lora_a: 131072 float4
        const float4* in4 = reinterpret_cast<const float4*>(la);
#pragma unroll
        for (int it = 0; it < 4; it++) {
            const size_t i = (size_t)it * 32768 + cb * 256 + tid;
            float4 v = in4[i];
            reinterpret_cast<__half2*>(g_ah)[i * 2]     = __floats2half2_rn(v.x, v.y);
            reinterpret_cast<__half2*>(g_ah)[i * 2 + 1] = __floats2half2_rn(v.z, v.w);
        }
    } else {
        const int i = (b - 672) * 256 + tid;           // over ODIM*LMAX = 32768
        const int o = i >> 3;
        const int l = i & 7;
        const float4* src = reinterpret_cast<const float4*>(lb + ((size_t)l * ODIM + o) * RANK);
        __half2 h[8];
#pragma unroll
        for (int q = 0; q < 4; q++) {
            float4 v = src[q];
            h[q * 2]     = __floats2half2_rn(v.x, v.y);
            h[q * 2 + 1] = __floats2half2_rn(v.z, v.w);
        }
        __half2* dst = reinterpret_cast<__half2*>(g_we + (size_t)o * KEXT + l * RANK);
        *reinterpret_cast<uint4*>(dst)     = *reinterpret_cast<uint4*>(h);
        *reinterpret_cast<uint4*>(dst + 4) = *reinterpret_cast<uint4*>(h + 4);
    }
}

// ---------------------------------------------------------------------------
// Tensor-core shrink (R13-proven): block = (adapter l, 64 gathered tokens).
// Per K-chunk of 64: x fp32 -> fp16 (regs) -> swizzled SMEM (+ STG to g_xh),
// A_l tile cp.async double-buffered; warps 0-3 accumulate s via m16n8k16.
// Epilogue writes one-hot fp16 rows of g_xe.
// ---------------------------------------------------------------------------
#define SH_CH   (DDIM / 64)          // 64 chunks
#define XT_B    (64 * 128)           // 8 KB x tile
#define AT_B    (16 * 128)           // 2 KB A tile

__global__ __launch_bounds__(256)
void shrink_mma(const float* __restrict__ x) {
    __shared__ __align__(16) char xt[2][XT_B];
    __shared__ __align__(16) char at[2][AT_B];
    __shared__ int toks[64];

    const int bid = blockIdx.x;
    const int l = bid & 7;
    const int start = (bid >> 3) * 64;
    const int cnt = g_cnt[l];
    if (start >= cnt) return;
    const int tid = threadIdx.x;
    const int wid = tid >> 5;
    const int lane = tid & 31;

    if (tid < 64)
        toks[tid] = (start + tid < cnt) ? g_tok[l * T_TOK + start + tid] : -1;
    __syncthreads();

    const uint32_t xt0 = smem_u32(&xt[0][0]);
    const uint32_t at0 = smem_u32(&at[0][0]);
    const __half* Al = g_ah + (size_t)l * RANK * DDIM;

    auto stage_a = [&](int ch) {
        const uint32_t dst = at0 + (uint32_t)(ch & 1) * AT_B;
        if (tid < 128) {                       // 16 rows x 8 units
            const int r = tid >> 3;
            const int c = tid & 7;
            cp16(dst + r * 128 + ((c ^ (r & 7)) << 4),
                 Al + (size_t)r * DDIM + ch * 64 + c * 8);
        }
        asm volatile("cp.async.commit_group;" ::: "memory");
    };

    const int u0r = tid >> 3, u0c = tid & 7;
    const int u1r = (tid + 256) >> 3, u1c = tid & 7;

    float acc[2][4];
#pragma unroll
    for (int n = 0; n < 2; n++)
#pragma unroll
        for (int q = 0; q < 4; q++) acc[n][q] = 0.f;

    const int a_r = lane & 15;
    const int a_h = lane >> 4;
    const int b_r = (lane & 7) + ((lane >> 4) << 3);
    const int b_h = (lane >> 3) & 1;

    stage_a(0);
    stage_a(1);

    for (int ch = 0; ch < SH_CH; ch++) {
        const int buf = ch & 1;
        uint4 pk[2];
        const int tA[2] = {toks[u0r], toks[u1r]};
#pragma unroll
        for (int u = 0; u < 2; u++) {
            const int c = u ? u1c : u0c;
            if (tA[u] >= 0) {
                const float4* src = reinterpret_cast<const float4*>(
                    x + (size_t)tA[u] * DDIM + ch * 64 + c * 8);
                float4 v0 = src[0], v1 = src[1];
                __half2 h0 = __floats2half2_rn(v0.x, v0.y);
                __half2 h1 = __floats2half2_rn(v0.z, v0.w);
                __half2 h2 = __floats2half2_rn(v1.x, v1.y);
                __half2 h3 = __floats2half2_rn(v1.z, v1.w);
                pk[u].x = *reinterpret_cast<uint32_t*>(&h0);
                pk[u].y = *reinterpret_cast<uint32_t*>(&h1);
                pk[u].z = *reinterpret_cast<uint32_t*>(&h2);
                pk[u].w = *reinterpret_cast<uint32_t*>(&h3);
            } else {
                pk[u] = make_uint4(0, 0, 0, 0);
            }
        }
        if (ch < SH_CH - 1)
            asm volatile("cp.async.wait_group 1;" ::: "memory");
        else
            asm volatile("cp.async.wait_group 0;" ::: "memory");
#pragma unroll
        for (int u = 0; u < 2; u++) {
            const int r = u ? u1r : u0r;
            const int c = u ? u1c : u0c;
            *reinterpret_cast<uint4*>(&xt[buf][r * 128 + ((c ^ (r & 7)) << 4)]) = pk[u];
            if (tA[u] >= 0)
                *reinterpret_cast<uint4*>(g_xh + (size_t)tA[u] * DDIM + ch * 64 + c * 8) = pk[u];
        }
        __syncthreads();
        if (wid < 4) {
            const uint32_t Xb = xt0 + (uint32_t)buf * XT_B;
            const uint32_t Ab = at0 + (uint32_t)buf * AT_B;
#pragma unroll
            for (int ks = 0; ks < 4; ks++) {
                uint32_t af[4], bf[4];
                const int rowa = wid * 16 + a_r;
                const int cla = ks * 2 + a_h;
                ldsm4(af, Xb + rowa * 128 + ((cla ^ (rowa & 7)) << 4));
                const int rowb = b_r;
                const int clb = ks * 2 + b_h;
                ldsm4(bf, Ab + rowb * 128 + ((clb ^ (rowb & 7)) << 4));
                mma_fp16(acc[0], af, bf[0], bf[1]);
                mma_fp16(acc[1], af, bf[2], bf[3]);
            }
        }
        __syncthreads();
        if (ch + 2 < SH_CH) stage_a(ch + 2);
    }

    // Epilogue A: zero the 7 other adapters' segments of each token row.
    for (int i = tid; i < 64 * 14; i += 256) {
        const int r = i / 14;
        int q = i % 14;
        if (q >= l * 2) q += 2;
        const int t = toks[r];
        if (t >= 0)
            reinterpret_cast<uint4*>(g_xe + (size_t)t * KEXT)[q] = make_uint4(0, 0, 0, 0);
    }
    // Epilogue B: warps 0-3 write s values (fp16) into own segment.
    if (wid < 4) {
        const int er = lane >> 2;
        const int ec = (lane & 3) * 2;
#pragma unroll
        for (int half = 0; half < 2; half++) {
            const int r = wid * 16 + er + half * 8;
            const int t = toks[r];
            if (t >= 0) {
#pragma unroll
                for (int nt = 0; nt < 2; nt++) {
                    __half2 v = __floats2half2_rn(acc[nt][half * 2], acc[nt][half * 2 + 1]);
                    *reinterpret_cast<__half2*>(
                        g_xe + (size_t)t * KEXT + l * RANK + nt * 8 + ec) = v;
                }
            }
        }
    }
}

// ---------------------------------------------------------------------------
// Fused GEMM: out = [x | S~] @ [W | B_cat]^T   (fp16 mma.sync, fp32 accum)
// 128x256 CTA tile, BK=64, 4-stage cp.async pipeline (192 KB SMEM), 8 warps.
// Cross-chunk fragment prefetch. (frozen) Also re-zeroes g_cnt for the next
// kernel_launch invocation (shrink, the last reader, has already completed).
// ---------------------------------------------------------------------------
#define BKC     64
#define NCHUNKC (KTOT / BKC)                  // 66
#define A_TILEB (128 * 128)
#define B_TILEB (256 * 128)
#define STAGEB  (A_TILEB + B_TILEB)           // 48 KB
#define STAGES  4
#define GEMM_SMEM (STAGES * STAGEB)           // 192 KB

__global__ __launch_bounds__(256, 1)
void gemm_mma(float* __restrict__ C) {
    extern __shared__ char smem[];
    const uint32_t sb = smem_u32(smem);
    const int tid  = threadIdx.x;
    const int wid  = tid >> 5;
    const int lane = tid & 31;

    if (blockIdx.x == 0 && tid < LMAX) g_cnt[tid] = 0;   // reset for next launch

    const int bid = blockIdx.x;
    const int TN = ODIM / 256;                 // 16
    const int GRP = 8;
    const int per = GRP * TN;                  // 128
    const int m_t = (bid / per) * GRP + (bid % per) % GRP;
    const int n_t = (bid % per) / GRP;
    const int bm = m_t * 128;
    const int bn = n_t * 256;

    const int warp_m = wid & 1;
    const int warp_n = wid >> 1;

    auto issue_chunk = [&](int chunk, int stage) {
        const int k0 = chunk * BKC;
        const bool ext = (k0 >= DDIM);
        const __half* asrc = ext ? g_xe : g_xh;
        const __half* bsrc = ext ? g_we : g_wh;
        const size_t astr = ext ? KEXT : DDIM;
        const int ak = ext ? (k0 - DDIM) : k0;
        const uint32_t sbase = sb + (uint32_t)stage * STAGEB;
#pragma unroll
        for (int rep = 0; rep < 4; rep++) {            // A: 1024 cp16
            const int idx = rep * 256 + tid;
            const int r = idx >> 3;
            const int c = idx & 7;
            const void* g = asrc + (size_t)(bm + r) * astr + ak + c * 8;
            cp16(sbase + r * 128 + ((c ^ (r & 7)) << 4), g);
        }
#pragma unroll
        for (int rep = 0; rep < 8; rep++) {            // B: 2048 cp16
            const int idx = rep * 256 + tid;
            const int r = idx >> 3;
            const int c = idx & 7;
            const void* g = bsrc + (size_t)(bn + r) * astr + ak + c * 8;
            cp16(sbase + A_TILEB + r * 128 + ((c ^ (r & 7)) << 4), g);
        }
        asm volatile("cp.async.commit_group;" ::: "memory");
    };

    const int a_r = lane & 15;
    const int a_h = lane >> 4;
    const int b_r = (lane & 7) + ((lane >> 4) << 3);
    const int b_h = (lane >> 3) & 1;

    auto load_frags = [&](int stage, int ks, uint32_t (&af)[4][4], uint32_t (&bf)[4][4]) {
        const uint32_t Ab = sb + (uint32_t)stage * STAGEB;
        const uint32_t Bb = Ab + A_TILEB;
        const int cla = ks * 2 + a_h;
        const int clb = ks * 2 + b_h;
#pragma unroll
        for (int mt = 0; mt < 4; mt++) {
            const int row = warp_m * 64 + mt * 16 + a_r;
            ldsm4(af[mt], Ab + row * 128 + ((cla ^ (row & 7)) << 4));
        }
#pragma unroll
        for (int p = 0; p < 4; p++) {
            const int row = warp_n * 64 + p * 16 + b_r;
            ldsm4(bf[p], Bb + row * 128 + ((clb ^ (row & 7)) << 4));
        }
    };

    float acc[4][8][4];
#pragma unroll
    for (int i = 0; i < 4; i++)
#pragma unroll
        for (int j = 0; j < 8; j++)
#pragma unroll
            for (int q = 0; q < 4; q++) acc[i][j][q] = 0.f;

#pragma unroll
    for (int s = 0; s < STAGES - 1; s++) issue_chunk(s, s);

    uint32_t af[2][4][4], bf[2][4][4];
    asm volatile("cp.async.wait_group %0;" :: "n"(STAGES - 2) : "memory");
    __syncthreads();
    load_frags(0, 0, af[0], bf[0]);

    for (int i = 0; i < NCHUNKC; i++) {
        const int stage = i & (STAGES - 1);
#pragma unroll
        for (int ks = 0; ks < 4; ks++) {
            const int cur = ks & 1;
            if (ks < 3) load_frags(stage, ks + 1, af[cur ^ 1], bf[cur ^ 1]);
#pragma unroll
            for (int mt = 0; mt < 4; mt++)
#pragma unroll
                for (int nt = 0; nt < 8; nt++)
                    mma_fp16(acc[mt][nt], af[cur][mt],
                             bf[cur][nt >> 1][(nt & 1) * 2],
                             bf[cur][nt >> 1][(nt & 1) * 2 + 1]);
        }
        if (i + 1 < NCHUNKC) {
            asm volatile("cp.async.wait_group 1;" ::: "memory");
            __syncthreads();
            load_frags((i + 1) & (STAGES - 1), 0, af[0], bf[0]);
            if (i + STAGES - 1 < NCHUNKC)
                issue_chunk(i + STAGES - 1, (i + STAGES - 1) & (STAGES - 1));
        }
    }

    const int er = lane >> 2;
    const int ec = (lane & 3) * 2;
#pragma unroll
    for (int mt = 0; mt < 4; mt++) {
#pragma unroll
        for (int nt = 0; nt < 8; nt++) {
            float* base = C + (size_t)(bm + warp_m * 64 + mt * 16 + er) * ODIM +
                          bn + warp_n * 64 + nt * 8 + ec;
            *reinterpret_cast<float2*>(base) =
                make_float2(acc[mt][nt][0], acc[mt][nt][1]);
            *reinterpret_cast<float2*>(base + 8 * ODIM) =
                make_float2(acc[mt][nt][2], acc[mt][nt][3]);
        }
    }
}

// ---------------------------------------------------------------------------
// Launch: inputs order: x, weight, lora_a, lora_b, token_lora_idx
// ---------------------------------------------------------------------------
extern "C" void kernel_launch(void* const* d_in, const int* in_sizes, int n_in,
                              void* d_out, int out_size) {
    const float* x   = (const float*)d_in[0];
    const float* w   = (const float*)d_in[1];
    const float* la  = (const float*)d_in[2];
    const float* lb  = (const float*)d_in[3];
    const int*   idx = (const int*)d_in[4];
    float* out = (float*)d_out;

    cudaFuncSetAttribute(gemm_mma, cudaFuncAttributeMaxDynamicSharedMemorySize,
                         GEMM_SMEM);

    conv_all<<<800, 256>>>(w, la, lb, idx);            // conversions + bucketing
    shrink_mma<<<LMAX * (T_TOK / 64), 256>>>(x);       // S~ + g_xh (R13-proven)
    gemm_mma<<<(T_TOK / 128) * (ODIM / 256), 256, GEMM_SMEM>>>(out);
}

// round 17
// speedup vs baseline: 1.0370x; 1.0045x over previous
#include <cuda_runtime.h>
#include <cuda_fp16.h>
#include <cstdint>

// Problem constants
#define T_TOK 8192
#define DDIM  4096
#define ODIM  4096
#define LMAX  8
#define RANK  16
#define KEXT  (LMAX * RANK)     // 128 extension columns
#define KTOT  (DDIM + KEXT)     // 4224

// ---------------------------------------------------------------------------
// Static device scratch (no allocations allowed)
// ---------------------------------------------------------------------------
__device__ __half g_xh[(size_t)T_TOK * DDIM];      // x  in fp16 (written by shrink)
__device__ __half g_wh[(size_t)ODIM * DDIM];       // W  in fp16
__device__ __half g_ah[(size_t)LMAX * RANK * DDIM];// lora_a in fp16 (1 MB)
__device__ __half g_xe[(size_t)T_TOK * KEXT];      // S~ one-hot shrink (2 MB)
__device__ __half g_we[(size_t)ODIM * KEXT];       // B_cat (1 MB)
__device__ int    g_cnt[LMAX];                     // per-adapter counts (zeroed by gemm)
__device__ int    g_tok[LMAX * T_TOK];             // per-adapter token lists

// ---------------------------------------------------------------------------
// PTX helpers (sm_80/90-era: legal on plain sm_103 target)
// ---------------------------------------------------------------------------
__device__ __forceinline__ uint32_t smem_u32(const void* p) {
    uint32_t a;
    asm("{ .reg .u64 t; cvta.to.shared.u64 t, %1; cvt.u32.u64 %0, t; }"
        : "=r"(a) : "l"(p));
    return a;
}
__device__ __forceinline__ void cp16(uint32_t d, const void* g) {
    asm volatile("cp.async.cg.shared.global [%0], [%1], 16;"
                 :: "r"(d), "l"(g) : "memory");
}
__device__ __forceinline__ void cp8(uint32_t d, const void* g) {
    asm volatile("cp.async.ca.shared.global [%0], [%1], 8;"
                 :: "r"(d), "l"(g) : "memory");
}
__device__ __forceinline__ void ldsm4(uint32_t* r, uint32_t a) {
    asm volatile("ldmatrix.sync.aligned.m8n8.x4.shared.b16 {%0,%1,%2,%3}, [%4];"
                 : "=r"(r[0]), "=r"(r[1]), "=r"(r[2]), "=r"(r[3]) : "r"(a));
}
__device__ __forceinline__ void mma_fp16(float* c, const uint32_t* a,
                                         uint32_t b0, uint32_t b1) {
    asm volatile(
        "mma.sync.aligned.m16n8k16.row.col.f32.f16.f16.f32 "
        "{%0,%1,%2,%3}, {%4,%5,%6,%7}, {%8,%9}, {%0,%1,%2,%3};"
        : "+f"(c[0]), "+f"(c[1]), "+f"(c[2]), "+f"(c[3])
        : "r"(a[0]), "r"(a[1]), "r"(a[2]), "r"(a[3]), "r"(b0), "r"(b1));
}

// ---------------------------------------------------------------------------
// conv_all: ONE launch for all conversions + token bucketing (R16-proven).
// ---------------------------------------------------------------------------
__global__ void conv_all(const float* __restrict__ w,
                         const float* __restrict__ la,
                         const float* __restrict__ lb,
                         const int*   __restrict__ idx) {
    const int b = blockIdx.x;
    const int tid = threadIdx.x;
    if (b < 32) {
        const int t = b * 256 + tid;                   // 8192 tokens
        const int l = idx[t];
        const int p = atomicAdd(&g_cnt[l], 1);
        g_tok[l * T_TOK + p] = t;
    } else if (b < 544) {
        const int cb = b - 32;
        size_t n4 = (size_t)ODIM * DDIM / 4;           // 4,194,304
        const float4* in4 = reinterpret_cast<const float4*>(w);
        for (size_t i = (size_t)cb * 256 + tid; i < n4; i += (size_t)512 * 256) {
            float4 v = in4[i];
            reinterpret_cast<__half2*>(g_wh)[i * 2]     = __floats2half2_rn(v.x, v.y);
            reinterpret_cast<__half2*>(g_wh)[i * 2 + 1] = __floats2half2_rn(v.z, v.w);
        }
    } else if (b < 672) {
        const int cb = b - 544;                        // lora_a: 131072 float4
        const float4* in4 = reinterpret_cast<const float4*>(la);
#pragma unroll
        for (int it = 0; it < 4; it++) {
            const size_t i = (size_t)it * 32768 + cb * 256 + tid;
            float4 v = in4[i];
            reinterpret_cast<__half2*>(g_ah)[i * 2]     = __floats2half2_rn(v.x, v.y);
            reinterpret_cast<__half2*>(g_ah)[i * 2 + 1] = __floats2half2_rn(v.z, v.w);
        }
    } else {
        const int i = (b - 672) * 256 + tid;           // over ODIM*LMAX = 32768
        const int o = i >> 3;
        const int l = i & 7;
        const float4* src = reinterpret_cast<const float4*>(lb + ((size_t)l * ODIM + o) * RANK);
        __half2 h[8];
#pragma unroll
        for (int q = 0; q < 4; q++) {
            float4 v = src[q];
            h[q * 2]     = __floats2half2_rn(v.x, v.y);
            h[q * 2 + 1] = __floats2half2_rn(v.z, v.w);
        }
        __half2* dst = reinterpret_cast<__half2*>(g_we + (size_t)o * KEXT + l * RANK);
        *reinterpret_cast<uint4*>(dst)     = *reinterpret_cast<uint4*>(h);
        *reinterpret_cast<uint4*>(dst + 4) = *reinterpret_cast<uint4*>(h + 4);
    }
}

// ---------------------------------------------------------------------------
// Tensor-core shrink with x register-prefetch: block = (adapter, 64 tokens).
// x LDG for chunk ch+1 issues before ch's MMA -> global latency hidden.
// A_l tile cp.async double-buffered (all 256 threads, 8B units).
// ---------------------------------------------------------------------------
#define SH_CH   (DDIM / 64)          // 64 chunks
#define XT_B    (64 * 128)           // 8 KB x tile
#define AT_B    (16 * 128)           // 2 KB A tile

__global__ __launch_bounds__(256)
void shrink_mma(const float* __restrict__ x) {
    __shared__ __align__(16) char xt[2][XT_B];
    __shared__ __align__(16) char at[2][AT_B];
    __shared__ int toks[64];

    const int bid = blockIdx.x;
    const int l = bid & 7;
    const int start = (bid >> 3) * 64;
    const int cnt = g_cnt[l];
    if (start >= cnt) return;
    const int tid = threadIdx.x;
    const int wid = tid >> 5;
    const int lane = tid & 31;

    if (tid < 64)
        toks[tid] = (start + tid < cnt) ? g_tok[l * T_TOK + start + tid] : -1;
    __syncthreads();

    const uint32_t xt0 = smem_u32(&xt[0][0]);
    const uint32_t at0 = smem_u32(&at[0][0]);
    const __half* Al = g_ah + (size_t)l * RANK * DDIM;

    auto stage_a = [&](int ch) {
        // 16 rows x 16 8B-units = 256 cp8 (all threads)
        const uint32_t dst = at0 + (uint32_t)(ch & 1) * AT_B;
        const int r = tid >> 4;               // 0..15
        const int c8 = tid & 15;              // 8B unit 0..15
        const uint32_t off = r * 128 + c8 * 8;
        const uint32_t sw = off ^ ((off >> 3) & 0x70);   // byte-level SW128
        cp8(dst + sw, Al + (size_t)r * DDIM + ch * 64 + c8 * 4);
        asm volatile("cp.async.commit_group;" ::: "memory");
    };

    const int u0r = tid >> 3, u0c = tid & 7;
    const int u1r = (tid + 256) >> 3, u1c = tid & 7;
    const int tA[2] = {toks[u0r], toks[u1r]};

    auto load_x = [&](int ch, uint4* pk) {
#pragma unroll
        for (int u = 0; u < 2; u++) {
            const int c = u ? u1c : u0c;
            if (tA[u] >= 0) {
                const float4* src = reinterpret_cast<const float4*>(
                    x + (size_t)tA[u] * DDIM + ch * 64 + c * 8);
                float4 v0 = src[0], v1 = src[1];
                __half2 h0 = __floats2half2_rn(v0.x, v0.y);
                __half2 h1 = __floats2half2_rn(v0.z, v0.w);
                __half2 h2 = __floats2half2_rn(v1.x, v1.y);
                __half2 h3 = __floats2half2_rn(v1.z, v1.w);
                pk[u].x = *reinterpret_cast<uint32_t*>(&h0);
                pk[u].y = *reinterpret_cast<uint32_t*>(&h1);
                pk[u].z = *reinterpret_cast<uint32_t*>(&h2);
                pk[u].w = *reinterpret_cast<uint32_t*>(&h3);
            } else {
                pk[u] = make_uint4(0, 0, 0, 0);
            }
        }
    };

    float acc[2][4];
#pragma unroll
    for (int n = 0; n < 2; n++)
#pragma unroll
        for (int q = 0; q < 4; q++) acc[n][q] = 0.f;

    const int a_r = lane & 15;
    const int a_h = lane >> 4;
    const int b_r = (lane & 7) + ((lane >> 4) << 3);
    const int b_h = (lane >> 3) & 1;

    stage_a(0);
    stage_a(1);

    uint4 pk[2], pk_next[2];
    load_x(0, pk);

    for (int ch = 0; ch < SH_CH; ch++) {
        const int buf = ch & 1;
        // A tile for this chunk resident
        if (ch < SH_CH - 1)
            asm volatile("cp.async.wait_group 1;" ::: "memory");
        else
            asm volatile("cp.async.wait_group 0;" ::: "memory");
        // STS x (swizzled) + STG fp16 to g_xh
#pragma unroll
        for (int u = 0; u < 2; u++) {
            const int r = u ? u1r : u0r;
            const int c = u ? u1c : u0c;
            *reinterpret_cast<uint4*>(&xt[buf][r * 128 + ((c ^ (r & 7)) << 4)]) = pk[u];
            if (tA[u] >= 0)
                *reinterpret_cast<uint4*>(g_xh + (size_t)tA[u] * DDIM + ch * 64 + c * 8) = pk[u];
        }
        __syncthreads();
        // Prefetch next chunk's x NOW (latency hidden under MMA + barriers)
        if (ch + 1 < SH_CH) load_x(ch + 1, pk_next);
        // MMA (warps 0-3)
        if (wid < 4) {
            const uint32_t Xb = xt0 + (uint32_t)buf * XT_B;
            const uint32_t Ab = at0 + (uint32_t)buf * AT_B;
#pragma unroll
            for (int ks = 0; ks < 4; ks++) {
                uint32_t af[4], bf[4];
                const int rowa = wid * 16 + a_r;
                const int cla = ks * 2 + a_h;
                ldsm4(af, Xb + rowa * 128 + ((cla ^ (rowa & 7)) << 4));
                const int rowb = b_r;
                const int clb = ks * 2 + b_h;
                ldsm4(bf, Ab + rowb * 128 + ((clb ^ (rowb & 7)) << 4));
                mma_fp16(acc[0], af, bf[0], bf[1]);
                mma_fp16(acc[1], af, bf[2], bf[3]);
            }
        }
        __syncthreads();
        if (ch + 2 < SH_CH) stage_a(ch + 2);
        pk[0] = pk_next[0];
        pk[1] = pk_next[1];
    }

    // Epilogue A: zero the 7 other adapters' segments of each token row.
    for (int i = tid; i < 64 * 14; i += 256) {
        const int r = i / 14;
        int q = i % 14;
        if (q >= l * 2) q += 2;
        const int t = toks[r];
        if (t >= 0)
            reinterpret_cast<uint4*>(g_xe + (size_t)t * KEXT)[q] = make_uint4(0, 0, 0, 0);
    }
    // Epilogue B: warps 0-3 write s values (fp16) into own segment.
    if (wid < 4) {
        const int er = lane >> 2;
        const int ec = (lane & 3) * 2;
#pragma unroll
        for (int half = 0; half < 2; half++) {
            const int r = wid * 16 + er + half * 8;
            const int t = toks[r];
            if (t >= 0) {
#pragma unroll
                for (int nt = 0; nt < 2; nt++) {
                    __half2 v = __floats2half2_rn(acc[nt][half * 2], acc[nt][half * 2 + 1]);
                    *reinterpret_cast<__half2*>(
                        g_xe + (size_t)t * KEXT + l * RANK + nt * 8 + ec) = v;
                }
            }
        }
    }
}

// ---------------------------------------------------------------------------
// Fused GEMM: out = [x | S~] @ [W | B_cat]^T   (fp16 mma.sync, fp32 accum)
// 128x256 CTA tile, BK=64, 4-stage cp.async pipeline (192 KB SMEM), 8 warps.
// Cross-chunk fragment prefetch. (frozen) Re-zeroes g_cnt for next launch.
// ---------------------------------------------------------------------------
#define BKC     64
#define NCHUNKC (KTOT / BKC)                  // 66
#define A_TILEB (128 * 128)
#define B_TILEB (256 * 128)
#define STAGEB  (A_TILEB + B_TILEB)           // 48 KB
#define STAGES  4
#define GEMM_SMEM (STAGES * STAGEB)           // 192 KB

__global__ __launch_bounds__(256, 1)
void gemm_mma(float* __restrict__ C) {
    extern __shared__ char smem[];
    const uint32_t sb = smem_u32(smem);
    const int tid  = threadIdx.x;
    const int wid  = tid >> 5;
    const int lane = tid & 31;

    if (blockIdx.x == 0 && tid < LMAX) g_cnt[tid] = 0;   // reset for next launch

    const int bid = blockIdx.x;
    const int TN = ODIM / 256;                 // 16
    const int GRP = 8;
    const int per = GRP * TN;                  // 128
    const int m_t = (bid / per) * GRP + (bid % per) % GRP;
    const int n_t = (bid % per) / GRP;
    const int bm = m_t * 128;
    const int bn = n_t * 256;

    const int warp_m = wid & 1;
    const int warp_n = wid >> 1;

    auto issue_chunk = [&](int chunk, int stage) {
        const int k0 = chunk * BKC;
        const bool ext = (k0 >= DDIM);
        const __half* asrc = ext ? g_xe : g_xh;
        const __half* bsrc = ext ? g_we : g_wh;
        const size_t astr = ext ? KEXT : DDIM;
        const int ak = ext ? (k0 - DDIM) : k0;
        const uint32_t sbase = sb + (uint32_t)stage * STAGEB;
#pragma unroll
        for (int rep = 0; rep < 4; rep++) {            // A: 1024 cp16
            const int idx = rep * 256 + tid;
            const int r = idx >> 3;
            const int c = idx & 7;
            const void* g = asrc + (size_t)(bm + r) * astr + ak + c * 8;
            cp16(sbase + r * 128 + ((c ^ (r & 7)) << 4), g);
        }
#pragma unroll
        for (int rep = 0; rep < 8; rep++) {            // B: 2048 cp16
            const int idx = rep * 256 + tid;
            const int r = idx >> 3;
            const int c = idx & 7;
            const void* g = bsrc + (size_t)(bn + r) * astr + ak + c * 8;
            cp16(sbase + A_TILEB + r * 128 + ((c ^ (r & 7)) << 4), g);
        }
        asm volatile("cp.async.commit_group;" ::: "memory");
    };

    const int a_r = lane & 15;
    const int a_h = lane >> 4;
    const int b_r = (lane & 7) + ((lane >> 4) << 3);
    const int b_h = (lane >> 3) & 1;

    auto load_frags = [&](int stage, int ks, uint32_t (&af)[4][4], uint32_t (&bf)[4][4]) {
        const uint32_t Ab = sb + (uint32_t)stage * STAGEB;
        const uint32_t Bb = Ab + A_TILEB;
        const int cla = ks * 2 + a_h;
        const int clb = ks * 2 + b_h;
#pragma unroll
        for (int mt = 0; mt < 4; mt++) {
            const int row = warp_m * 64 + mt * 16 + a_r;
            ldsm4(af[mt], Ab + row * 128 + ((cla ^ (row & 7)) << 4));
        }
#pragma unroll
        for (int p = 0; p < 4; p++) {
            const int row = warp_n * 64 + p * 16 + b_r;
            ldsm4(bf[p], Bb + row * 128 + ((clb ^ (row & 7)) << 4));
        }
    };

    float acc[4][8][4];
#pragma unroll
    for (int i = 0; i < 4; i++)
#pragma unroll
        for (int j = 0; j < 8; j++)
#pragma unroll
            for (int q = 0; q < 4; q++) acc[i][j][q] = 0.f;

#pragma unroll
    for (int s = 0; s < STAGES - 1; s++) issue_chunk(s, s);

    uint32_t af[2][4][4], bf[2][4][4];
    asm volatile("cp.async.wait_group %0;" :: "n"(STAGES - 2) : "memory");
    __syncthreads();
    load_frags(0, 0, af[0], bf[0]);

    for (int i = 0; i < NCHUNKC; i++) {
        const int stage = i & (STAGES - 1);
#pragma unroll
        for (int ks = 0; ks < 4; ks++) {
            const int cur = ks & 1;
            if (ks < 3) load_frags(stage, ks + 1, af[cur ^ 1], bf[cur ^ 1]);
#pragma unroll
            for (int mt = 0; mt < 4; mt++)
#pragma unroll
                for (int nt = 0; nt < 8; nt++)
                    mma_fp16(acc[mt][nt], af[cur][mt],
                             bf[cur][nt >> 1][(nt & 1) * 2],
                             bf[cur][nt >> 1][(nt & 1) * 2 + 1]);
        }
        if (i + 1 < NCHUNKC) {
            asm volatile("cp.async.wait_group 1;" ::: "memory");
            __syncthreads();
            load_frags((i + 1) & (STAGES - 1), 0, af[0], bf[0]);
            if (i + STAGES - 1 < NCHUNKC)
                issue_chunk(i + STAGES - 1, (i + STAGES - 1) & (STAGES - 1));
        }
    }

    const int er = lane >> 2;
    const int ec = (lane & 3) * 2;
#pragma unroll
    for (int mt = 0; mt < 4; mt++) {
#pragma unroll
        for (int nt = 0; nt < 8; nt++) {
            float* base = C + (size_t)(bm + warp_m * 64 + mt * 16 + er) * ODIM +
                          bn + warp_n * 64 + nt * 8 + ec;
            *reinterpret_cast<float2*>(base) =
                make_float2(acc[mt][nt][0], acc[mt][nt][1]);
            *reinterpret_cast<float2*>(base + 8 * ODIM) =
                make_float2(acc[mt][nt][2], acc[mt][nt][3]);
        }
    }
}

// ---------------------------------------------------------------------------
// Launch: inputs order: x, weight, lora_a, lora_b, token_lora_idx
// ---------------------------------------------------------------------------
extern "C" void kernel_launch(void* const* d_in, const int* in_sizes, int n_in,
                              void* d_out, int out_size) {
    const float* x   = (const float*)d_in[0];
    const float* w   = (const float*)d_in[1];
    const float* la  = (const float*)d_in[2];
    const float* lb  = (const float*)d_in[3];
    const int*   idx = (const int*)d_in[4];
    float* out = (float*)d_out;

    cudaFuncSetAttribute(gemm_mma, cudaFuncAttributeMaxDynamicSharedMemorySize,
                         GEMM_SMEM);

    conv_all<<<800, 256>>>(w, la, lb, idx);            // conversions + bucketing
    shrink_mma<<<LMAX * (T_TOK / 64), 256>>>(x);       // S~ + g_xh (x-prefetch)
    gemm_mma<<<(T_TOK / 128) * (ODIM / 256), 256, GEMM_SMEM>>>(out);
}